// round 2
// baseline (speedup 1.0000x reference)
#include <cuda_runtime.h>

// Problem constants
#define B_DIM   8
#define N_DIM   512
#define HIST    24
#define SKIP    256
#define ENDC    128
#define KSZ     13
#define FUT     12
#define OUTD    2
#define THREADS 128

// Packed f32x2 FMA (sm_100+). ptxas never emits this from C++ — PTX only.
__device__ __forceinline__ unsigned long long ffma2(unsigned long long a,
                                                    unsigned long long b,
                                                    unsigned long long c) {
    unsigned long long d;
    asm("fma.rn.f32x2 %0, %1, %2, %3;" : "=l"(d) : "l"(a), "l"(b), "l"(c));
    return d;
}
__device__ __forceinline__ float lo32(unsigned long long v) {
    return __uint_as_float((unsigned)(v & 0xffffffffull));
}
__device__ __forceinline__ float hi32(unsigned long long v) {
    return __uint_as_float((unsigned)(v >> 32));
}

// One CTA per (b,n) node. 128 threads; thread tid owns hidden channel e=tid.
// Stage 1: h[t][e] = relu( sum_d relu(x[t][d]) * W1[lbl][e][d] + b1[lbl][e] )
// Stage 2: out[f][o] = sum_{k,e} h[f+k][e] * W2[lbl][o][e][k] + b2[lbl][o]
__global__ __launch_bounds__(THREADS, 6)
void tcnn_moe_kernel(const float* __restrict__ x,
                     const int*   __restrict__ labels,
                     const float* __restrict__ W1,
                     const float* __restrict__ b1,
                     const float* __restrict__ W2,
                     const float* __restrict__ b2,
                     float* __restrict__ out) {
    __shared__ __align__(16) float xs[HIST * SKIP];   // 24 KB relu(x) tile
    __shared__ __align__(16) float hs[HIST * ENDC];   // 12 KB hidden tile
    __shared__ float red[4][FUT * OUTD];              // cross-warp reduction

    const int node = blockIdx.x;
    const int tid  = threadIdx.x;
    const int lbl  = labels[node];

    // ---- cooperative load of x with relu (coalesced float4) ----
    const float4* xg  = reinterpret_cast<const float4*>(x + (size_t)node * (HIST * SKIP));
    float4*       xs4 = reinterpret_cast<float4*>(xs);
    #pragma unroll
    for (int i = 0; i < (HIST * SKIP / 4) / THREADS; ++i) {
        float4 v = xg[tid + i * THREADS];
        v.x = fmaxf(v.x, 0.f); v.y = fmaxf(v.y, 0.f);
        v.z = fmaxf(v.z, 0.f); v.w = fmaxf(v.w, 0.f);
        xs4[tid + i * THREADS] = v;
    }
    __syncthreads();

    // ---- stage 1: packed-f32x2 GEMV per output channel ----
    unsigned long long acc2[HIST];
    #pragma unroll
    for (int t = 0; t < HIST; ++t) acc2[t] = 0ull;

    const ulonglong2* wp = reinterpret_cast<const ulonglong2*>(
        W1 + ((size_t)lbl * ENDC + tid) * SKIP);
    const ulonglong2* xp = reinterpret_cast<const ulonglong2*>(xs);

    #pragma unroll 2
    for (int d4 = 0; d4 < SKIP / 4; ++d4) {
        ulonglong2 w = wp[d4];                      // W1[e][4d..4d+3], L1/L2 resident
        #pragma unroll
        for (int t = 0; t < HIST; ++t) {
            ulonglong2 xv = xp[t * (SKIP / 4) + d4];  // uniform addr -> LDS broadcast
            acc2[t] = ffma2(w.y, xv.y, ffma2(w.x, xv.x, acc2[t]));
        }
    }

    const float bias1 = b1[lbl * ENDC + tid];
    #pragma unroll
    for (int t = 0; t < HIST; ++t) {
        float v = lo32(acc2[t]) + hi32(acc2[t]) + bias1;
        hs[t * ENDC + tid] = fmaxf(v, 0.f);
    }
    __syncthreads();

    // ---- stage 2: per-channel partial conv, then reduce over e ----
    float ht[HIST];
    #pragma unroll
    for (int t = 0; t < HIST; ++t) ht[t] = hs[t * ENDC + tid];  // conflict-free columns

    // Batch-load both W2 rows up front (MLP ~26 instead of serialized loads)
    float wa[KSZ], wb[KSZ];
    const float* w2a = W2 + ((size_t)(lbl * OUTD + 0) * ENDC + tid) * KSZ;
    const float* w2b = W2 + ((size_t)(lbl * OUTD + 1) * ENDC + tid) * KSZ;
    #pragma unroll
    for (int k = 0; k < KSZ; ++k) { wa[k] = __ldg(w2a + k); wb[k] = __ldg(w2b + k); }

    float p[FUT * OUTD];
    #pragma unroll
    for (int j = 0; j < FUT * OUTD; ++j) p[j] = 0.f;

    #pragma unroll
    for (int k = 0; k < KSZ; ++k) {
        #pragma unroll
        for (int f = 0; f < FUT; ++f) {
            p[f * 2 + 0] = fmaf(ht[f + k], wa[k], p[f * 2 + 0]);
            p[f * 2 + 1] = fmaf(ht[f + k], wb[k], p[f * 2 + 1]);
        }
    }

    // butterfly reduce within warp
    #pragma unroll
    for (int j = 0; j < FUT * OUTD; ++j) {
        float v = p[j];
        #pragma unroll
        for (int off = 16; off; off >>= 1)
            v += __shfl_xor_sync(0xffffffffu, v, off);
        p[j] = v;
    }
    const int warp = tid >> 5, lane = tid & 31;
    if (lane == 0) {
        #pragma unroll
        for (int j = 0; j < FUT * OUTD; ++j) red[warp][j] = p[j];
    }
    __syncthreads();

    if (tid < FUT * OUTD) {
        const int j = tid;                 // j = f*2 + o
        float v = red[0][j] + red[1][j] + red[2][j] + red[3][j]
                + b2[lbl * OUTD + (j & 1)];
        out[(size_t)node * (FUT * OUTD) + j] = v;
    }
}

extern "C" void kernel_launch(void* const* d_in, const int* in_sizes, int n_in,
                              void* d_out, int out_size) {
    const float* x      = (const float*)d_in[0];
    const int*   labels = (const int*)  d_in[1];
    const float* W1     = (const float*)d_in[2];
    const float* b1     = (const float*)d_in[3];
    const float* W2     = (const float*)d_in[4];
    const float* b2     = (const float*)d_in[5];
    float* out = (float*)d_out;

    const int nodes = in_sizes[1];   // B*N = 4096 (cluster_labels element count)
    tcnn_moe_kernel<<<nodes, THREADS>>>(x, labels, W1, b1, W2, b2, out);
}

// round 3
// speedup vs baseline: 1.5765x; 1.5765x over previous
#include <cuda_runtime.h>

// Problem constants
#define B_DIM   8
#define N_DIM   512
#define HIST    24
#define SKIP    256
#define ENDC    128
#define KSZ     13
#define FUT     12
#define OUTD    2
#define THREADS 128

#define CHUNK_D   16                    // d-values per W1 smem chunk
#define NCHUNK    (SKIP / CHUNK_D)      // 16
#define WPITCH    20                    // floats per channel row (16 + 4 pad): conflict-free, 16B-aligned

// Packed f32x2 FMA (sm_100+). ptxas never emits this from C++ — PTX only.
__device__ __forceinline__ unsigned long long ffma2(unsigned long long a,
                                                    unsigned long long b,
                                                    unsigned long long c) {
    unsigned long long d;
    asm("fma.rn.f32x2 %0, %1, %2, %3;" : "=l"(d) : "l"(a), "l"(b), "l"(c));
    return d;
}
__device__ __forceinline__ float lo32(unsigned long long v) {
    return __uint_as_float((unsigned)(v & 0xffffffffull));
}
__device__ __forceinline__ float hi32(unsigned long long v) {
    return __uint_as_float((unsigned)(v >> 32));
}

// One CTA per (b,n) node. 128 threads.
// Stage 1: warp w owns timesteps [6w, 6w+6); lane l owns channels {l, l+32, l+64, l+96}.
//          h[t][e] = relu( sum_d relu(x[t][d]) * W1[lbl][e][d] + b1[lbl][e] )
//          W1 rows streamed through smem (cp.async double buffer, coalesced).
// Stage 2: out[f][o] = sum_{k,e} h[f+k][e] * W2[lbl][o][e][k] + b2[lbl][o]
__global__ __launch_bounds__(THREADS, 4)
void tcnn_moe_kernel(const float* __restrict__ x,
                     const int*   __restrict__ labels,
                     const float* __restrict__ W1,
                     const float* __restrict__ b1,
                     const float* __restrict__ W2,
                     const float* __restrict__ b2,
                     float* __restrict__ out) {
    __shared__ __align__(16) float xs[HIST * SKIP];            // 24 KB relu(x) tile
    __shared__ __align__(16) float wbuf[2][ENDC * WPITCH];     // 20 KB W1 double buffer
    __shared__ float red[4][FUT * OUTD];
    float* hs = &wbuf[0][0];                                   // 12 KB hidden tile, aliases dead W bufs

    const int node = blockIdx.x;
    const int tid  = threadIdx.x;
    const int lbl  = labels[node];
    const int w    = tid >> 5;
    const int l    = tid & 31;
    const int t0   = w * 6;

    // ---- cooperative load of x with relu (coalesced float4) ----
    const float4* xg  = reinterpret_cast<const float4*>(x + (size_t)node * (HIST * SKIP));
    float4*       xs4 = reinterpret_cast<float4*>(xs);
    #pragma unroll
    for (int i = 0; i < (HIST * SKIP / 4) / THREADS; ++i) {
        float4 v = xg[tid + i * THREADS];
        v.x = fmaxf(v.x, 0.f); v.y = fmaxf(v.y, 0.f);
        v.z = fmaxf(v.z, 0.f); v.w = fmaxf(v.w, 0.f);
        xs4[tid + i * THREADS] = v;
    }

    // ---- W1 chunk producer: thread tid fetches row tid's 64B slice (coalesced 16B cp.async) ----
    const unsigned wsm = (unsigned)__cvta_generic_to_shared(&wbuf[0][0]);
    const float* wrow = W1 + ((size_t)lbl * ENDC + tid) * SKIP;

    #define ISSUE_CHUNK(c)                                                             \
        do {                                                                           \
            const float* _src = wrow + (c) * CHUNK_D;                                  \
            unsigned _dst = wsm + (((c) & 1) * ENDC * WPITCH + tid * WPITCH) * 4u;     \
            asm volatile("cp.async.ca.shared.global [%0], [%1], 16;\n"                 \
                         "cp.async.ca.shared.global [%2], [%3], 16;\n"                 \
                         "cp.async.ca.shared.global [%4], [%5], 16;\n"                 \
                         "cp.async.ca.shared.global [%6], [%7], 16;\n"                 \
                         "cp.async.commit_group;\n" ::                                 \
                         "r"(_dst),      "l"(_src),                                    \
                         "r"(_dst + 16), "l"(_src + 4),                                \
                         "r"(_dst + 32), "l"(_src + 8),                                \
                         "r"(_dst + 48), "l"(_src + 12) : "memory");                   \
        } while (0)

    ISSUE_CHUNK(0);

    // ---- stage 1 mainloop ----
    unsigned long long acc2[4][6];
    #pragma unroll
    for (int j = 0; j < 4; ++j)
        #pragma unroll
        for (int tt = 0; tt < 6; ++tt) acc2[j][tt] = 0ull;

    for (int c = 0; c < NCHUNK; ++c) {
        if (c + 1 < NCHUNK) {
            ISSUE_CHUNK(c + 1);
            asm volatile("cp.async.wait_group 1;" ::: "memory");
        } else {
            asm volatile("cp.async.wait_group 0;" ::: "memory");
        }
        __syncthreads();   // chunk c visible to all; also covers the initial x-tile fill at c==0

        const float* wb = &wbuf[c & 1][0];
        #pragma unroll
        for (int dd = 0; dd < CHUNK_D / 4; ++dd) {
            const int d4 = c * (CHUNK_D / 4) + dd;
            ulonglong2 xv[6];
            #pragma unroll
            for (int tt = 0; tt < 6; ++tt)   // uniform address across warp -> LDS broadcast
                xv[tt] = *reinterpret_cast<const ulonglong2*>(&xs[(t0 + tt) * SKIP + d4 * 4]);
            #pragma unroll
            for (int j = 0; j < 4; ++j) {
                ulonglong2 wv = *reinterpret_cast<const ulonglong2*>(
                    &wb[(l + 32 * j) * WPITCH + dd * 4]);
                #pragma unroll
                for (int tt = 0; tt < 6; ++tt)
                    acc2[j][tt] = ffma2(wv.y, xv[tt].y, ffma2(wv.x, xv[tt].x, acc2[j][tt]));
            }
        }
        __syncthreads();   // all reads of buf (c&1) done before it is re-filled / aliased
    }

    // ---- bias + relu + store h (hs aliases wbuf; safe after trailing sync) ----
    #pragma unroll
    for (int j = 0; j < 4; ++j) {
        const int ch = l + 32 * j;
        const float bias1 = b1[lbl * ENDC + ch];
        #pragma unroll
        for (int tt = 0; tt < 6; ++tt) {
            float v = lo32(acc2[j][tt]) + hi32(acc2[j][tt]) + bias1;
            hs[(t0 + tt) * ENDC + ch] = fmaxf(v, 0.f);
        }
    }
    __syncthreads();

    // ---- stage 2: per-channel partial conv, then reduce over e ----
    float ht[HIST];
    #pragma unroll
    for (int t = 0; t < HIST; ++t) ht[t] = hs[t * ENDC + tid];  // conflict-free columns

    float wa[KSZ], wb2[KSZ];
    const float* w2a = W2 + ((size_t)(lbl * OUTD + 0) * ENDC + tid) * KSZ;
    const float* w2b = W2 + ((size_t)(lbl * OUTD + 1) * ENDC + tid) * KSZ;
    #pragma unroll
    for (int k = 0; k < KSZ; ++k) { wa[k] = __ldg(w2a + k); wb2[k] = __ldg(w2b + k); }

    float p[FUT * OUTD];
    #pragma unroll
    for (int j = 0; j < FUT * OUTD; ++j) p[j] = 0.f;

    #pragma unroll
    for (int k = 0; k < KSZ; ++k) {
        #pragma unroll
        for (int f = 0; f < FUT; ++f) {
            p[f * 2 + 0] = fmaf(ht[f + k], wa[k],  p[f * 2 + 0]);
            p[f * 2 + 1] = fmaf(ht[f + k], wb2[k], p[f * 2 + 1]);
        }
    }

    #pragma unroll
    for (int j = 0; j < FUT * OUTD; ++j) {
        float v = p[j];
        #pragma unroll
        for (int off = 16; off; off >>= 1)
            v += __shfl_xor_sync(0xffffffffu, v, off);
        p[j] = v;
    }
    if (l == 0) {
        #pragma unroll
        for (int j = 0; j < FUT * OUTD; ++j) red[w][j] = p[j];
    }
    __syncthreads();

    if (tid < FUT * OUTD) {
        const int j = tid;                 // j = f*2 + o
        float v = red[0][j] + red[1][j] + red[2][j] + red[3][j]
                + b2[lbl * OUTD + (j & 1)];
        out[(size_t)node * (FUT * OUTD) + j] = v;
    }
}

extern "C" void kernel_launch(void* const* d_in, const int* in_sizes, int n_in,
                              void* d_out, int out_size) {
    const float* x      = (const float*)d_in[0];
    const int*   labels = (const int*)  d_in[1];
    const float* W1     = (const float*)d_in[2];
    const float* b1     = (const float*)d_in[3];
    const float* W2     = (const float*)d_in[4];
    const float* b2     = (const float*)d_in[5];
    float* out = (float*)d_out;

    const int nodes = in_sizes[1];   // B*N = 4096 (cluster_labels element count)
    tcnn_moe_kernel<<<nodes, THREADS>>>(x, labels, W1, b1, W2, b2, out);
}